// round 6
// baseline (speedup 1.0000x reference)
#include <cuda_runtime.h>

// Scratch (device globals — no allocations allowed)
__device__ float g_k1[2 * 441 * 64];          // [b*441+sp][c]
__device__ float g_v [2 * 64 * 441];          // [b*64+c][21*21]
__device__ float g_logits[2 * 25 * 441 * 64]; // [(b*25+g)*441 + d][c]

// ---------------------------------------------------------------------------
// Kernel A: k1 depthwise conv1d (effective 64 taps) + depthwise 3x3 conv for v
// ---------------------------------------------------------------------------
__global__ void prep_kernel(const float* __restrict__ x,
                            const float* __restrict__ wk,
                            const float* __restrict__ bk,
                            const float* __restrict__ wv,
                            const float* __restrict__ bv) {
    int e = blockIdx.x;
    if (e < 882) {
        // k1[b,d,c] = bk[d] + sum_t x[b,t,d] * wk[d, t + 220 - c]
        int b = e / 441, d = e - b * 441;
        __shared__ float xs[64];
        __shared__ float wks[128];   // wk[d, 157..283]
        int t = threadIdx.x;
        if (t < 64) xs[t] = x[(b * 64 + t) * 441 + d];
        if (t < 127) wks[t] = wk[d * 441 + 157 + t];
        __syncthreads();
        if (t < 64) {
            float acc = bk[d];
#pragma unroll
            for (int tt = 0; tt < 64; tt++)
                acc += xs[tt] * wks[tt + 63 - t];   // (tt+220-t) - 157
            g_k1[e * 64 + t] = acc;
        }
    } else {
        // depthwise 3x3 conv, pad 1: v[b,ch,y,x]
        int id = e - 882;              // [0,128)
        int b = id >> 6, ch = id & 63;
        float w[9];
#pragma unroll
        for (int i = 0; i < 9; i++) w[i] = wv[ch * 9 + i];
        float bias = bv[ch];
        const float* xp = x + (b * 64 + ch) * 441;
        for (int p = threadIdx.x; p < 441; p += blockDim.x) {
            int y = p / 21, xx = p - y * 21;
            float acc = bias;
#pragma unroll
            for (int dy = 0; dy < 3; dy++) {
                int yy = y + dy - 1;
                if (yy < 0 || yy >= 21) continue;
#pragma unroll
                for (int dx = 0; dx < 3; dx++) {
                    int xx2 = xx + dx - 1;
                    if (xx2 < 0 || xx2 >= 21) continue;
                    acc += xp[yy * 21 + xx2] * w[dy * 3 + dx];
                }
            }
            g_v[id * 441 + p] = acc;
        }
    }
}

// ---------------------------------------------------------------------------
// Kernel B: logits. Block = (b, g, d-tile of 112). 200 blocks x 512 threads.
//   load w1/w2-slice/gather -> att1 (25x64, redundant per tile) -> logits
// SMEM floats: w1s 1252 | kqs 3200 | r1 1600 | w2s 2804  (= 8856, ~35KB)
// ---------------------------------------------------------------------------
#define BT 512

__global__ __launch_bounds__(BT) void logits_kernel(
                            const float* __restrict__ x,
                            const float* __restrict__ w1,
                            const float* __restrict__ bng,
                            const float* __restrict__ bnb,
                            const float* __restrict__ bnm,
                            const float* __restrict__ bnv,
                            const float* __restrict__ w2,
                            const float* __restrict__ b2) {
    __shared__ float smem[8856];
    float* w1s = smem;           // 1250 (pad 1252)
    float* kqs = smem + 1252;    // 50 x 64
    float* r1  = smem + 4452;    // 25 x 64 (16B aligned: 4452*4=17808)
    float* w2s = smem + 6052;    // up to 112 x 25

    int bid = blockIdx.x;
    int b = bid / 100;
    int rem = bid - b * 100;
    int g  = rem >> 2;
    int dt = rem & 3;
    int d0 = dt * 112;
    int dn = min(112, 441 - d0);
    int ph = g / 5, pw = g - ph * 5;
    int tid = threadIdx.x;

    // loads (one phase)
    for (int i = tid; i < 1250; i += BT) w1s[i] = w1[g * 1250 + i];
    {
        const float* src = w2 + g * 11025 + d0 * 25;
        for (int i = tid; i < dn * 25; i += BT) w2s[i] = src[i];
    }
    // gather kq: u = i2*64 + c2 enumerates (s, c, ij)
    for (int u = tid; u < 3200; u += BT) {
        int s = u / 1600; int rm = u - s * 1600;
        int c = rm / 25;  int ij = rm - c * 25;
        int i5 = ij / 5, j5 = ij - i5 * 5;
        int row = 5 * i5 + ph, col = 5 * j5 + pw;
        float v = 0.f;
        if (row < 21 && col < 21) {
            int sp = row * 21 + col;
            v = (s == 0) ? x[(b * 64 + c) * 441 + sp]
                         : g_k1[(b * 441 + sp) * 64 + c];
        }
        kqs[u] = v;
    }
    __syncthreads();

    // att1: r1[o][c2] (25 x 64), BN + ReLU
    for (int idx = tid; idx < 1600; idx += BT) {
        int o = idx >> 6, c2 = idx & 63;
        float acc = 0.f;
#pragma unroll
        for (int i = 0; i < 50; i++) acc += w1s[o * 50 + i] * kqs[i * 64 + c2];
        int go = g * 25 + o;
        float inv = bng[go] * rsqrtf(bnv[go] + 1e-5f);
        acc = (acc - bnm[go]) * inv + bnb[go];
        r1[idx] = fmaxf(acc, 0.f);
    }
    __syncthreads();

    // logits: dn x 64, blocked 4d x 4c; items = ceil(dn/4) * 16 <= 448
    int ndg = (dn + 3) >> 2;
    const float* b2g = b2 + g * 441 + d0;
    float* Lg = g_logits + ((size_t)(b * 25 + g) * 441 + d0) * 64;
    if (tid < ndg * 16) {
        int dg = tid >> 4, cg = tid & 15;
        int dl0 = dg * 4;
        int dl1 = min(dl0 + 1, dn - 1), dl2 = min(dl0 + 2, dn - 1), dl3 = min(dl0 + 3, dn - 1);
        float4 A0 = {0,0,0,0}, A1 = {0,0,0,0}, A2 = {0,0,0,0}, A3 = {0,0,0,0};
#pragma unroll 5
        for (int o = 0; o < 25; o++) {
            float4 r = *(const float4*)&r1[o * 64 + cg * 4];
            float v0 = w2s[dl0 * 25 + o];
            float v1 = w2s[dl1 * 25 + o];
            float v2 = w2s[dl2 * 25 + o];
            float v3 = w2s[dl3 * 25 + o];
            A0.x += v0*r.x; A0.y += v0*r.y; A0.z += v0*r.z; A0.w += v0*r.w;
            A1.x += v1*r.x; A1.y += v1*r.y; A1.z += v1*r.z; A1.w += v1*r.w;
            A2.x += v2*r.x; A2.y += v2*r.y; A2.z += v2*r.z; A2.w += v2*r.w;
            A3.x += v3*r.x; A3.y += v3*r.y; A3.z += v3*r.z; A3.w += v3*r.w;
        }
        int cc = cg * 4;
        {
            float bb = b2g[dl0];
            float4 o0 = {A0.x+bb, A0.y+bb, A0.z+bb, A0.w+bb};
            *(float4*)&Lg[dl0 * 64 + cc] = o0;
        }
        if (dl0 + 1 < dn) {
            float bb = b2g[dl1];
            float4 o1 = {A1.x+bb, A1.y+bb, A1.z+bb, A1.w+bb};
            *(float4*)&Lg[(dl0 + 1) * 64 + cc] = o1;
        }
        if (dl0 + 2 < dn) {
            float bb = b2g[dl2];
            float4 o2 = {A2.x+bb, A2.y+bb, A2.z+bb, A2.w+bb};
            *(float4*)&Lg[(dl0 + 2) * 64 + cc] = o2;
        }
        if (dl0 + 3 < dn) {
            float bb = b2g[dl3];
            float4 o3 = {A3.x+bb, A3.y+bb, A3.z+bb, A3.w+bb};
            *(float4*)&Lg[(dl0 + 3) * 64 + cc] = o3;
        }
    }
}

// ---------------------------------------------------------------------------
// Kernel D: softmax + value dot. Block = (b, g, c-quarter). 200 x 256 threads.
//   stage logits 441x16 -> softmax -> 64-term value dot -> out (+k1 residual)
// SMEM floats: Ls 7056 | red 256 | cmax 16 | csum 16
// ---------------------------------------------------------------------------
#define DT 256

__global__ __launch_bounds__(DT) void final_kernel(float* __restrict__ out) {
    __shared__ float Ls[7056];
    __shared__ float red[256];
    __shared__ float cmax[16];
    __shared__ float csum[16];

    int bid = blockIdx.x;
    int b = bid / 100;
    int rem = bid - b * 100;
    int g = rem >> 2;
    int q = rem & 3;
    int cbase = q * 16;
    int ph = g / 5, pw = g - ph * 5;
    int tid = threadIdx.x;

    // stage logits quarter (coalesced)
    const float* Lg = g_logits + (size_t)(b * 25 + g) * 28224 + cbase;
    for (int idx = tid; idx < 7056; idx += DT) {
        int d = idx >> 4, cl = idx & 15;
        Ls[idx] = Lg[d * 64 + cl];
    }
    __syncthreads();

    // softmax over d per column; 16 rows x 16 cols
    int cl = tid & 15, r = tid >> 4;
    {
        float pm = -1e30f;
        for (int d = r; d < 441; d += 16) pm = fmaxf(pm, Ls[d * 16 + cl]);
        red[r * 16 + cl] = pm;
        __syncthreads();
        if (tid < 16) {
            float m = red[tid];
#pragma unroll
            for (int r2 = 1; r2 < 16; r2++) m = fmaxf(m, red[r2 * 16 + tid]);
            cmax[tid] = m;
        }
        __syncthreads();
        float mm = cmax[cl];
        float ps = 0.f;
        for (int d = r; d < 441; d += 16) {
            float e = __expf(Ls[d * 16 + cl] - mm);
            Ls[d * 16 + cl] = e;
            ps += e;
        }
        __syncthreads();
        red[r * 16 + cl] = ps;
        __syncthreads();
        if (tid < 16) {
            float s2 = 0.f;
#pragma unroll
            for (int r2 = 0; r2 < 16; r2++) s2 += red[r2 * 16 + tid];
            csum[tid] = 1.f / s2;
        }
        __syncthreads();
    }

    // final dot: positions (h,w) with h%5==ph, w%5==pw, h,w in [2,23)
    int hl[5], wl[5]; int nh = 0, nw = 0;
    for (int h = ph; h < 23; h += 5) if (h >= 2) hl[nh++] = h;
    for (int w = pw; w < 23; w += 5) if (w >= 2) wl[nw++] = w;
    int npos = nh * nw;
    for (int item = tid; item < npos * 16; item += DT) {
        int p = item >> 4, c4 = item & 15;
        int h = hl[p / nw], w = wl[p % nw];
        int c = cbase + c4;
        float acc = 0.f;
        if (h >= 4 && w >= 4) {
            const float* vp = g_v + (b * 64) * 441 + (h - 4) * 21 + (w - 4);
            const float* lp = Ls + (220 - c) * 16 + c4;
#pragma unroll 8
            for (int t = 0; t < 64; t++)
                acc += vp[t * 441] * lp[t * 16];
        }
        acc *= csum[c4];
        if (h < 21 && w < 21) acc += g_k1[(b * 441 + h * 21 + w) * 64 + c];
        out[((b * 64 + c) * 21 + (h - 2)) * 21 + (w - 2)] = acc;
    }
}

extern "C" void kernel_launch(void* const* d_in, const int* in_sizes, int n_in,
                              void* d_out, int out_size) {
    const float* x   = (const float*)d_in[0];
    const float* wk  = (const float*)d_in[1];
    const float* bk  = (const float*)d_in[2];
    const float* w1  = (const float*)d_in[3];
    const float* bng = (const float*)d_in[4];
    const float* bnb = (const float*)d_in[5];
    const float* bnm = (const float*)d_in[6];
    const float* bnv = (const float*)d_in[7];
    const float* w2  = (const float*)d_in[8];
    const float* b2  = (const float*)d_in[9];
    const float* wv  = (const float*)d_in[10];
    const float* bv  = (const float*)d_in[11];
    float* out = (float*)d_out;

    prep_kernel<<<1010, 128>>>(x, wk, bk, wv, bv);
    logits_kernel<<<200, BT>>>(x, w1, bng, bnb, bnm, bnv, w2, b2);
    final_kernel<<<200, DT>>>(out);
}

// round 7
// speedup vs baseline: 1.6989x; 1.6989x over previous
#include <cuda_runtime.h>
#include <cstdint>

// Scratch (device globals — no allocations allowed)
__device__ float g_k1[2 * 441 * 64];   // [b*441+sp][c]
__device__ float g_v [2 * 64 * 441];   // [b*64+c][21*21]

__device__ __forceinline__ void cpa4(uint32_t saddr, const void* gaddr) {
    asm volatile("cp.async.ca.shared.global [%0], [%1], 4;" :: "r"(saddr), "l"(gaddr));
}

// ---------------------------------------------------------------------------
// Kernel 1: k1 depthwise conv1d (both batches per block) + depthwise 3x3 for v
// ---------------------------------------------------------------------------
__global__ void prep_kernel(const float* __restrict__ x,
                            const float* __restrict__ wk,
                            const float* __restrict__ bk,
                            const float* __restrict__ wv,
                            const float* __restrict__ bv) {
    int e = blockIdx.x;
    if (e < 441) {
        // k1[b,d,c] = bk[d] + sum_t x[b,t,d] * wk[d, t + 220 - c]
        int d = e;
        __shared__ float xs[128];    // [b][t]
        __shared__ float wks[128];   // wk[d, 157..283]
        int t = threadIdx.x;         // 128 threads
        {
            int b = t >> 6, tt = t & 63;
            xs[t] = x[(b * 64 + tt) * 441 + d];
        }
        if (t < 127) wks[t] = wk[d * 441 + 157 + t];
        __syncthreads();
        {
            int b = t >> 6, c = t & 63;
            const float* xb = xs + b * 64;
            float acc = bk[d];
#pragma unroll
            for (int tt = 0; tt < 64; tt++)
                acc += xb[tt] * wks[tt + 63 - c];
            g_k1[(b * 441 + d) * 64 + c] = acc;
        }
    } else {
        // depthwise 3x3 conv, pad 1: v[b,ch,y,x]
        int id = e - 441;              // [0,128)
        int b = id >> 6, ch = id & 63;
        float w[9];
#pragma unroll
        for (int i = 0; i < 9; i++) w[i] = wv[ch * 9 + i];
        float bias = bv[ch];
        const float* xp = x + (b * 64 + ch) * 441;
        for (int p = threadIdx.x; p < 441; p += blockDim.x) {
            int y = p / 21, xx = p - y * 21;
            float acc = bias;
#pragma unroll
            for (int dy = 0; dy < 3; dy++) {
                int yy = y + dy - 1;
                if (yy < 0 || yy >= 21) continue;
#pragma unroll
                for (int dx = 0; dx < 3; dx++) {
                    int xx2 = xx + dx - 1;
                    if (xx2 < 0 || xx2 >= 21) continue;
                    acc += xp[yy * 21 + xx2] * w[dy * 3 + dx];
                }
            }
            g_v[id * 441 + p] = acc;
        }
    }
}

// ---------------------------------------------------------------------------
// Kernel 2: per (b, g, c-quarter of 16):
//   P0: cp.async w2 | load w1 | stage vs | gather kq
//   att1 -> logits+exp+partial sums (no max; logits are O(0.05)) ->
//   16-thread sum reduce -> value dot (SMEM) -> out (+k1 residual)
// ---------------------------------------------------------------------------
#define NT 512
#define NC 16
// SMEM floats: w1s 1252 | kqs 800 | r1 400 | w2s 11028 | es 2032 | vs 1600 |
//              red 224 | csum 16   = 17352 floats = 69408 B
#define SM_FLOATS (1252 + 800 + 400 + 11028 + 2032 + 1600 + 224 + 16)

__global__ __launch_bounds__(NT, 2) void main_kernel(
                            const float* __restrict__ x,
                            const float* __restrict__ w1,
                            const float* __restrict__ bng,
                            const float* __restrict__ bnb,
                            const float* __restrict__ bnm,
                            const float* __restrict__ bnv,
                            const float* __restrict__ w2,
                            const float* __restrict__ b2,
                            float* __restrict__ out) {
    extern __shared__ float sm[];
    float* w1s  = sm;             // 1250 (pad 1252)
    float* kqs  = sm + 1252;      // 50 x 16
    float* r1   = sm + 2052;      // 25 x 16  (8208 B: 16B aligned)
    float* w2s  = sm + 2452;      // 441 x 25 (pad 11028)
    float* es   = sm + 13480;     // 127 x 16 (live d range 157..283)
    float* vs   = sm + 15512;     // 64 x 25
    float* red  = sm + 17112;     // 14 x 16
    float* csum = sm + 17336;     // 16

    int bid  = blockIdx.x;
    int b    = bid / 100;
    int rem  = bid - b * 100;
    int g    = rem >> 2;
    int q    = rem & 3;
    int cbase = q * NC;
    int ph = g / 5, pw = g - ph * 5;
    int tid = threadIdx.x;

    // ---- P0: async-stage w2[g] (43KB) into SMEM; overlapped past att1 ----
    {
        const float* src = w2 + g * 11025;
        uint32_t sbase = (uint32_t)__cvta_generic_to_shared(w2s);
        for (int i = tid; i < 11025; i += NT)
            cpa4(sbase + 4u * i, src + i);
        asm volatile("cp.async.commit_group;");
    }

    // position lists (all threads, registers)
    int hl[5], wl[5]; int nh = 0, nw = 0;
    for (int h = ph; h < 23; h += 5) if (h >= 2) hl[nh++] = h;
    for (int w = pw; w < 23; w += 5) if (w >= 2) wl[nw++] = w;
    int npos = nh * nw;

    // load w1[g]
    for (int i = tid; i < 1250; i += NT) w1s[i] = w1[g * 1250 + i];

    // stage value vectors vs[t][p] for this block's output positions
    for (int idx = tid; idx < (npos << 6); idx += NT) {
        int p = idx >> 6, t = idx & 63;
        int h = hl[p / nw], w = wl[p % nw];
        float v = 0.f;
        if (h >= 4 && w >= 4)
            v = g_v[(b * 64 + t) * 441 + (h - 4) * 21 + (w - 4)];
        vs[t * 25 + p] = v;
    }

    // gather kq[i2][cl]: u = i2*64 + (cbase+cl) -> (s, c, ij)
    for (int idx = tid; idx < 800; idx += NT) {
        int i2 = idx >> 4, cl = idx & 15;
        int u = i2 * 64 + cbase + cl;
        int s = u / 1600; int rm = u - s * 1600;
        int c = rm / 25;  int ij = rm - c * 25;
        int i5 = ij / 5, j5 = ij - i5 * 5;
        int row = 5 * i5 + ph, col = 5 * j5 + pw;
        float v = 0.f;
        if (row < 21 && col < 21) {
            int sp = row * 21 + col;
            v = (s == 0) ? x[(b * 64 + c) * 441 + sp]
                         : g_k1[(b * 441 + sp) * 64 + c];
        }
        kqs[idx] = v;
    }
    __syncthreads();

    // ---- att1 (25 x 16) = w1[g] (25x50) @ kq (50x16), BN + ReLU ----
    if (tid < 400) {
        int o = tid >> 4, cl = tid & 15;
        float acc = 0.f;
#pragma unroll
        for (int i = 0; i < 50; i++) acc += w1s[o * 50 + i] * kqs[i * NC + cl];
        int go = g * 25 + o;
        float inv = bng[go] * rsqrtf(bnv[go] + 1e-5f);
        acc = (acc - bnm[go]) * inv + bnb[go];
        r1[tid] = fmaxf(acc, 0.f);
    }
    asm volatile("cp.async.wait_group 0;" ::: "memory");
    __syncthreads();

    // ---- logits + exp + per-column partial sums (4d x 4c per thread) ----
    const float* b2g = b2 + g * 441;
    if (tid < 448) {                      // 14 full warps; dg in [0,112)
        int dg = tid >> 2, cg = tid & 3;
        int d0 = dg * 4;
        int dk0 = min(d0, 440), dk1 = min(d0 + 1, 440);
        int dk2 = min(d0 + 2, 440), dk3 = min(d0 + 3, 440);
        float4 A0 = {0,0,0,0}, A1 = {0,0,0,0}, A2 = {0,0,0,0}, A3 = {0,0,0,0};
        if (d0 < 441) {
#pragma unroll 5
            for (int o = 0; o < 25; o++) {
                float4 r = *(const float4*)&r1[o * NC + cg * 4];
                float v0 = w2s[dk0 * 25 + o];
                float v1 = w2s[dk1 * 25 + o];
                float v2 = w2s[dk2 * 25 + o];
                float v3 = w2s[dk3 * 25 + o];
                A0.x += v0*r.x; A0.y += v0*r.y; A0.z += v0*r.z; A0.w += v0*r.w;
                A1.x += v1*r.x; A1.y += v1*r.y; A1.z += v1*r.z; A1.w += v1*r.w;
                A2.x += v2*r.x; A2.y += v2*r.y; A2.z += v2*r.z; A2.w += v2*r.w;
                A3.x += v3*r.x; A3.y += v3*r.y; A3.z += v3*r.z; A3.w += v3*r.w;
            }
        }
        float s0 = 0.f, s1 = 0.f, s2 = 0.f, s3 = 0.f;
#define DO_ROW(Ai, di)                                                        \
        if ((di) < 441) {                                                     \
            float bb = b2g[di];                                               \
            float ex = __expf(Ai.x + bb), ey = __expf(Ai.y + bb);             \
            float ez = __expf(Ai.z + bb), ew = __expf(Ai.w + bb);             \
            s0 += ex; s1 += ey; s2 += ez; s3 += ew;                           \
            if ((di) >= 157 && (di) < 284) {                                  \
                float* E = &es[((di) - 157) * NC + cg * 4];                   \
                E[0] = ex; E[1] = ey; E[2] = ez; E[3] = ew;                   \
            }                                                                 \
        }
        DO_ROW(A0, d0)
        DO_ROW(A1, d0 + 1)
        DO_ROW(A2, d0 + 2)
        DO_ROW(A3, d0 + 3)
#undef DO_ROW
        // warp reduce over the 8 dg's in each warp (lanes with same lane&3)
#pragma unroll
        for (int off = 4; off <= 16; off <<= 1) {
            s0 += __shfl_xor_sync(0xFFFFFFFFu, s0, off);
            s1 += __shfl_xor_sync(0xFFFFFFFFu, s1, off);
            s2 += __shfl_xor_sync(0xFFFFFFFFu, s2, off);
            s3 += __shfl_xor_sync(0xFFFFFFFFu, s3, off);
        }
        int lane = tid & 31, wrp = tid >> 5;
        if (lane < 4) {
            float4 o4 = {s0, s1, s2, s3};
            *(float4*)&red[wrp * 16 + lane * 4] = o4;   // cols lane*4..+3
        }
    }
    __syncthreads();

    if (tid < 16) {
        float s = 0.f;
#pragma unroll
        for (int w = 0; w < 14; w++) s += red[w * 16 + tid];
        csum[tid] = 1.f / s;
    }
    __syncthreads();

    // ---- final dot: all operands in SMEM ----
    if (tid < npos * NC) {
        int p = tid >> 4, c4 = tid & 15;
        int h = hl[p / nw], w = wl[p % nw];
        int c = cbase + c4;
        float acc = 0.f;
        if (h >= 4 && w >= 4) {
            const float* vp = vs + p;
            const float* lp = es + (63 - c) * NC + c4;   // d=220-c+t -> row 63-c+t
#pragma unroll 8
            for (int t = 0; t < 64; t++)
                acc += vp[t * 25] * lp[t * NC];
        }
        acc *= csum[c4];
        if (h < 21 && w < 21) acc += g_k1[(b * 441 + h * 21 + w) * 64 + c];
        out[((b * 64 + c) * 21 + (h - 2)) * 21 + (w - 2)] = acc;
    }
}

extern "C" void kernel_launch(void* const* d_in, const int* in_sizes, int n_in,
                              void* d_out, int out_size) {
    const float* x   = (const float*)d_in[0];
    const float* wk  = (const float*)d_in[1];
    const float* bk  = (const float*)d_in[2];
    const float* w1  = (const float*)d_in[3];
    const float* bng = (const float*)d_in[4];
    const float* bnb = (const float*)d_in[5];
    const float* bnm = (const float*)d_in[6];
    const float* bnv = (const float*)d_in[7];
    const float* w2  = (const float*)d_in[8];
    const float* b2  = (const float*)d_in[9];
    const float* wv  = (const float*)d_in[10];
    const float* bv  = (const float*)d_in[11];
    float* out = (float*)d_out;

    cudaFuncSetAttribute(main_kernel, cudaFuncAttributeMaxDynamicSharedMemorySize,
                         SM_FLOATS * (int)sizeof(float));

    prep_kernel<<<569, 128>>>(x, wk, bk, wv, bv);
    main_kernel<<<200, NT, SM_FLOATS * (int)sizeof(float)>>>(
        x, w1, bng, bnb, bnm, bnv, w2, b2, out);
}